// round 11
// baseline (speedup 1.0000x reference)
#include <cuda_runtime.h>
#include <math.h>

#define T_  512
#define B_  2048
#define I_  24
#define H_  20

// Scratch xg[t][b][u] = float4(i,f,g,o). 8 pad timesteps so recur's depth-4
// prefetch (reads up to t ~ mylen+6) stays in-bounds.
__device__ float4 g_xg[(size_t)(T_ + 8) * B_ * H_];
// h[t][b][u] for the head pass.
__device__ float  g_h[(size_t)T_ * B_ * H_];

__device__ __forceinline__ float tanhx(float x) {
    float r; asm("tanh.approx.f32 %0,%1;" : "=f"(r) : "f"(x)); return r;
}
__device__ __forceinline__ float sigx(float x) {   // sigmoid via HW tanh
    return fmaf(0.5f, tanhx(0.5f * x), 0.5f);
}

// ---------------------------------------------------------------------------
// Kernel 1: xg = x @ W_ih^T + (b_ih+b_hh) for t < len[b].
// ONE SCALAR GATE PER THREAD: thread = (col j 0..3, unit u, gate g).
// 320 threads/block over 4 consecutive b (near-equal lengths, sorted) and a
// 64-step t-chunk. Per thread: 24 weight regs (one gate row), per t: 6
// lane-uniform LDG.128 (L1 broadcast; hit after first toucher), 24 FMA in
// two 12-deep chains, 1 coalesced STG.32 (tid = j*80+u*4+g matches the
// [t][b][u] float4 element order exactly). ~60 regs -> ~30 warps/SM.
// ---------------------------------------------------------------------------
#define XG_CHUNK 64
__global__ __launch_bounds__(320, 3)
void xg_kernel(const float* __restrict__ x,
               const int*   __restrict__ lens,
               const float* __restrict__ Wih,
               const float* __restrict__ bih,
               const float* __restrict__ bhh)
{
    const int slab = blockIdx.x >> 3;         // 0..511 (4 b each)
    const int chn  = blockIdx.x & 7;          // 0..7
    const int t0   = chn * XG_CHUNK;
    const int b0   = slab * 4;

    const int lmax = lens[b0];                // max length in slab (sorted)
    if (t0 >= lmax) return;                   // whole chunk masked
    const int tend = min(t0 + XG_CHUNK, lmax);

    const int tid = threadIdx.x;
    const int j   = tid / 80;                 // column 0..3
    const int r   = tid % 80;                 // = u*4 + g
    const int u   = r >> 2;
    const int g   = r & 3;
    const int b   = b0 + j;
    const int mylen = lens[b];

    // One gate row of W_ih (PyTorch row = g*H + u)
    float w[I_];
    #pragma unroll
    for (int k = 0; k < I_; k++) w[k] = Wih[(g * H_ + u) * I_ + k];
    const float bias = bih[g * H_ + u] + bhh[g * H_ + u];

    const float4* xbase = (const float4*)(x + (size_t)b * I_);
    const size_t  xstr  = (size_t)B_ * I_ / 4;        // per-t, in float4s
    float*        op    = (float*)g_xg + ((size_t)t0 * B_ + b) * (4 * H_) + r;
    const size_t  ostr  = (size_t)B_ * 4 * H_;        // per-t, in floats

    for (int t = t0; t < tend; t++) {
        const float4* p = xbase + (size_t)t * xstr;
        float4 v0 = p[0], v1 = p[1], v2 = p[2];
        float4 v3 = p[3], v4 = p[4], v5 = p[5];
        float xv[I_] = { v0.x,v0.y,v0.z,v0.w, v1.x,v1.y,v1.z,v1.w,
                         v2.x,v2.y,v2.z,v2.w, v3.x,v3.y,v3.z,v3.w,
                         v4.x,v4.y,v4.z,v4.w, v5.x,v5.y,v5.z,v5.w };

        float a0 = bias, a1 = 0.0f;           // two 12-deep FMA chains
        #pragma unroll
        for (int k = 0; k < I_; k += 2) {
            a0 = fmaf(w[k],     xv[k],     a0);
            a1 = fmaf(w[k + 1], xv[k + 1], a1);
        }

        if (t < mylen) *op = a0 + a1;         // coalesced STG.32
        op += ostr;
    }
}

// ---------------------------------------------------------------------------
// Kernel 2: recurrence, one warp per batch element, t < len[b] only.
// Gate loads coalesced (320B/warp-step), prefetched FOUR steps ahead via a
// rotated register buffer. Steps past mylen compute on in-bounds pad garbage
// but never store.  (Unchanged — proven ~150us.)
// ---------------------------------------------------------------------------
__global__ __launch_bounds__(128, 4)
void recur_kernel(const int*   __restrict__ lens,
                  const float* __restrict__ Whh)
{
    const int lane = threadIdx.x & 31;
    const int wid  = threadIdx.x >> 5;
    const int j    = blockIdx.x;
    const int b    = (wid < 2) ? (2*j + wid) : (2047 - 2*j - (wid - 2));
    const int uu   = (lane < H_) ? lane : 0;      // lanes 20..31 mirror u=0

    float wi[H_], wf[H_], wg[H_], wo[H_];
    #pragma unroll
    for (int k = 0; k < H_; k++) {
        wi[k] = Whh[(0*H_ + uu) * H_ + k];
        wf[k] = Whh[(1*H_ + uu) * H_ + k];
        wg[k] = Whh[(2*H_ + uu) * H_ + k];
        wo[k] = Whh[(3*H_ + uu) * H_ + k];
    }
    const int mylen = lens[b];                    // >= 1

    float h = 0.0f, c = 0.0f;

    const float4* xp = &g_xg[(size_t)b * H_ + uu];
    const size_t  xstride = (size_t)B_ * H_;
    float4 q0 = xp[0];
    float4 q1 = xp[xstride];
    float4 q2 = xp[2*xstride];
    float4 q3 = xp[3*xstride];
    xp += 4 * xstride;                            // next refill row

    float* hp = &g_h[(size_t)b * H_ + lane];

    #define RSTEP(QBUF, TOFF)                                            \
    {                                                                    \
        float ai = QBUF.x, af = QBUF.y, ag = QBUF.z, ao = QBUF.w;        \
        _Pragma("unroll")                                                \
        for (int k = 0; k < H_; k++) {                                   \
            float hk = __shfl_sync(0xffffffffu, h, k);                   \
            ai = fmaf(wi[k], hk, ai);                                    \
            af = fmaf(wf[k], hk, af);                                    \
            ag = fmaf(wg[k], hk, ag);                                    \
            ao = fmaf(wo[k], hk, ao);                                    \
        }                                                                \
        c = fmaf(sigx(af), c, sigx(ai) * tanhx(ag));                     \
        h = sigx(ao) * tanhx(c);                                         \
        if (lane < H_ && (t + TOFF) < mylen)                             \
            hp[(size_t)(t + TOFF) * (B_ * H_)] = h;                      \
        QBUF = *xp;                               /* refill t+TOFF+4 */  \
        xp += xstride;                                                   \
    }

    for (int t = 0; t < mylen; t += 4) {
        RSTEP(q0, 0)
        RSTEP(q1, 1)
        RSTEP(q2, 2)
        RSTEP(q3, 3)
    }
    #undef RSTEP
}

// ---------------------------------------------------------------------------
// Kernel 3: heads + padding over the full [T, B] grid.
// ---------------------------------------------------------------------------
__global__ __launch_bounds__(256)
void head_kernel(const int*   __restrict__ lens,
                 const float* __restrict__ Wa,
                 const float* __restrict__ ba,
                 const float* __restrict__ Wb,
                 const float* __restrict__ bb,
                 float* __restrict__ out)
{
    const int idx = blockIdx.x * 256 + threadIdx.x;   // t*B + b
    const int b   = idx & (B_ - 1);
    const int t   = idx >> 11;

    float za = ba[0], zb = bb[0];
    if (t < lens[b]) {
        float4 hq[5];
        const float4* hp = (const float4*)&g_h[(size_t)idx * H_];
        #pragma unroll
        for (int q = 0; q < 5; q++) hq[q] = hp[q];
        const float* hv = (const float*)hq;
        #pragma unroll
        for (int k = 0; k < H_; k++) {
            za = fmaf(hv[k], Wa[k], za);
            zb = fmaf(hv[k], Wb[k], zb);
        }
    }
    out[idx] = __expf(za);
    out[(size_t)T_ * B_ + idx] =
        fmaxf(zb, 0.0f) + __logf(1.0f + __expf(-fabsf(zb)));
}

extern "C" void kernel_launch(void* const* d_in, const int* in_sizes, int n_in,
                              void* d_out, int out_size)
{
    const float *x = 0, *Wih = 0, *Whh = 0, *bih = 0, *bhh = 0;
    const float *Wa = 0, *ba = 0, *Wb = 0, *bb = 0;
    const int *lens = 0;
    int seen80 = 0, seen20 = 0, seen1 = 0;
    for (int i = 0; i < n_in; i++) {
        int s = in_sizes[i];
        if      (s == T_ * B_ * I_) x    = (const float*)d_in[i];
        else if (s == B_)           lens = (const int*)d_in[i];
        else if (s == 4*H_ * I_)    Wih  = (const float*)d_in[i];
        else if (s == 4*H_ * H_)    Whh  = (const float*)d_in[i];
        else if (s == 4*H_) { if (seen80++ == 0) bih = (const float*)d_in[i]; else bhh = (const float*)d_in[i]; }
        else if (s == H_)   { if (seen20++ == 0) Wa  = (const float*)d_in[i]; else Wb  = (const float*)d_in[i]; }
        else if (s == 1)    { if (seen1++  == 0) ba  = (const float*)d_in[i]; else bb  = (const float*)d_in[i]; }
    }

    float* out = (float*)d_out;
    xg_kernel<<<512 * 8, 320>>>(x, lens, Wih, bih, bhh);
    recur_kernel<<<512, 128>>>(lens, Whh);
    head_kernel<<<(T_ * B_) / 256, 256>>>(lens, Wa, ba, Wb, bb, out);
}

// round 12
// speedup vs baseline: 1.6899x; 1.6899x over previous
#include <cuda_runtime.h>
#include <math.h>

#define T_  512
#define B_  2048
#define I_  24
#define H_  20

// Scratch xg[t][b][u] = float4(i,f,g,o). 8 pad timesteps so recur's depth-4
// prefetch (reads up to t ~ mylen+6) stays in-bounds.
__device__ float4 g_xg[(size_t)(T_ + 8) * B_ * H_];
// h[t][b][u] for the head pass.
__device__ float  g_h[(size_t)T_ * B_ * H_];

__device__ __forceinline__ float tanhx(float x) {
    float r; asm("tanh.approx.f32 %0,%1;" : "=f"(r) : "f"(x)); return r;
}
__device__ __forceinline__ float sigx(float x) {   // sigmoid via HW tanh
    return fmaf(0.5f, tanhx(0.5f * x), 0.5f);
}

// ---------------------------------------------------------------------------
// Kernel 1: xg = x @ W_ih^T + (b_ih+b_hh) for t < len[b].
// Thread = (column j 0..3, unit u, gate-pair p): 48 weight regs (2 gate
// rows). SOFTWARE-PIPELINED over t: a separate register buffer holds x[t+1],
// whose 6 LDG.128 issue a full iteration (~400 SMSP-cyc at 15 warps/SM)
// before consumption -> memory latency hidden (round-10 exposed it, issue
// 25%). Per t: 48 FMA + 1 coalesced float2 STG (tid = j*40+u*2+p matches
// the [t][b][u] float4 element order). 4 consecutive b per block.
// ---------------------------------------------------------------------------
#define XG_CHUNK 64
__global__ __launch_bounds__(160, 3)
void xg_kernel(const float* __restrict__ x,
               const int*   __restrict__ lens,
               const float* __restrict__ Wih,
               const float* __restrict__ bih,
               const float* __restrict__ bhh)
{
    const int slab = blockIdx.x >> 3;         // 0..511 (4 b each)
    const int chn  = blockIdx.x & 7;          // 0..7
    const int t0   = chn * XG_CHUNK;
    const int b0   = slab * 4;

    const int lmax = lens[b0];                // max length in slab (sorted)
    if (t0 >= lmax) return;                   // whole chunk masked
    const int tend = min(t0 + XG_CHUNK, lmax);

    const int tid = threadIdx.x;
    const int j   = tid / 40;                 // column 0..3
    const int r   = tid % 40;
    const int u   = r >> 1;                   // unit 0..19
    const int p   = r & 1;                    // gate pair: 0=(i,f) 1=(g,o)
    const int b   = b0 + j;
    const int mylen = lens[b];

    const int g0 = 2 * p, g1 = 2 * p + 1;
    float w0[I_], w1[I_];
    #pragma unroll
    for (int k = 0; k < I_; k++) {
        w0[k] = Wih[(g0 * H_ + u) * I_ + k];
        w1[k] = Wih[(g1 * H_ + u) * I_ + k];
    }
    float2 bias;
    bias.x = bih[g0 * H_ + u] + bhh[g0 * H_ + u];
    bias.y = bih[g1 * H_ + u] + bhh[g1 * H_ + u];

    const size_t xstr = (size_t)B_ * I_ / 4;              // per-t, in float4s
    const size_t ostr = (size_t)B_ * H_ * 2;              // per-t, in float2s
    const float4* xbase = (const float4*)(x + (size_t)b * I_);
    float2* op = (float2*)g_xg + ((size_t)t0 * B_ + b) * H_ * 2 + u * 2 + p;

    // prologue: load x[t0] into the current buffer
    float4 c0, c1, c2, c3, c4, c5;
    {
        const float4* pc = xbase + (size_t)t0 * xstr;
        c0 = pc[0]; c1 = pc[1]; c2 = pc[2];
        c3 = pc[3]; c4 = pc[4]; c5 = pc[5];
    }

    #pragma unroll 2
    for (int t = t0; t < tend; t++) {
        // prefetch x[t+1] (clamped; consumed next iteration)
        const float4* pn = xbase + (size_t)min(t + 1, T_ - 1) * xstr;
        float4 n0 = pn[0], n1 = pn[1], n2 = pn[2];
        float4 n3 = pn[3], n4 = pn[4], n5 = pn[5];

        const float xv[I_] = { c0.x,c0.y,c0.z,c0.w, c1.x,c1.y,c1.z,c1.w,
                               c2.x,c2.y,c2.z,c2.w, c3.x,c3.y,c3.z,c3.w,
                               c4.x,c4.y,c4.z,c4.w, c5.x,c5.y,c5.z,c5.w };
        float2 a = bias;
        #pragma unroll
        for (int k = 0; k < I_; k++) {
            a.x = fmaf(w0[k], xv[k], a.x);
            a.y = fmaf(w1[k], xv[k], a.y);
        }

        if (t < mylen) *op = a;               // coalesced float2 store
        op += ostr;

        c0 = n0; c1 = n1; c2 = n2; c3 = n3; c4 = n4; c5 = n5;
    }
}

// ---------------------------------------------------------------------------
// Kernel 2: recurrence, one warp per batch element, t < len[b] only.
// Gate loads coalesced (320B/warp-step), prefetched FOUR steps ahead via a
// rotated register buffer. Steps past mylen compute on in-bounds pad garbage
// but never store.  (Unchanged — proven ~150us.)
// ---------------------------------------------------------------------------
__global__ __launch_bounds__(128, 4)
void recur_kernel(const int*   __restrict__ lens,
                  const float* __restrict__ Whh)
{
    const int lane = threadIdx.x & 31;
    const int wid  = threadIdx.x >> 5;
    const int j    = blockIdx.x;
    const int b    = (wid < 2) ? (2*j + wid) : (2047 - 2*j - (wid - 2));
    const int uu   = (lane < H_) ? lane : 0;      // lanes 20..31 mirror u=0

    float wi[H_], wf[H_], wg[H_], wo[H_];
    #pragma unroll
    for (int k = 0; k < H_; k++) {
        wi[k] = Whh[(0*H_ + uu) * H_ + k];
        wf[k] = Whh[(1*H_ + uu) * H_ + k];
        wg[k] = Whh[(2*H_ + uu) * H_ + k];
        wo[k] = Whh[(3*H_ + uu) * H_ + k];
    }
    const int mylen = lens[b];                    // >= 1

    float h = 0.0f, c = 0.0f;

    const float4* xp = &g_xg[(size_t)b * H_ + uu];
    const size_t  xstride = (size_t)B_ * H_;
    float4 q0 = xp[0];
    float4 q1 = xp[xstride];
    float4 q2 = xp[2*xstride];
    float4 q3 = xp[3*xstride];
    xp += 4 * xstride;                            // next refill row

    float* hp = &g_h[(size_t)b * H_ + lane];

    #define RSTEP(QBUF, TOFF)                                            \
    {                                                                    \
        float ai = QBUF.x, af = QBUF.y, ag = QBUF.z, ao = QBUF.w;        \
        _Pragma("unroll")                                                \
        for (int k = 0; k < H_; k++) {                                   \
            float hk = __shfl_sync(0xffffffffu, h, k);                   \
            ai = fmaf(wi[k], hk, ai);                                    \
            af = fmaf(wf[k], hk, af);                                    \
            ag = fmaf(wg[k], hk, ag);                                    \
            ao = fmaf(wo[k], hk, ao);                                    \
        }                                                                \
        c = fmaf(sigx(af), c, sigx(ai) * tanhx(ag));                     \
        h = sigx(ao) * tanhx(c);                                         \
        if (lane < H_ && (t + TOFF) < mylen)                             \
            hp[(size_t)(t + TOFF) * (B_ * H_)] = h;                      \
        QBUF = *xp;                               /* refill t+TOFF+4 */  \
        xp += xstride;                                                   \
    }

    for (int t = 0; t < mylen; t += 4) {
        RSTEP(q0, 0)
        RSTEP(q1, 1)
        RSTEP(q2, 2)
        RSTEP(q3, 3)
    }
    #undef RSTEP
}

// ---------------------------------------------------------------------------
// Kernel 3: heads + padding over the full [T, B] grid.
// ---------------------------------------------------------------------------
__global__ __launch_bounds__(256)
void head_kernel(const int*   __restrict__ lens,
                 const float* __restrict__ Wa,
                 const float* __restrict__ ba,
                 const float* __restrict__ Wb,
                 const float* __restrict__ bb,
                 float* __restrict__ out)
{
    const int idx = blockIdx.x * 256 + threadIdx.x;   // t*B + b
    const int b   = idx & (B_ - 1);
    const int t   = idx >> 11;

    float za = ba[0], zb = bb[0];
    if (t < lens[b]) {
        float4 hq[5];
        const float4* hp = (const float4*)&g_h[(size_t)idx * H_];
        #pragma unroll
        for (int q = 0; q < 5; q++) hq[q] = hp[q];
        const float* hv = (const float*)hq;
        #pragma unroll
        for (int k = 0; k < H_; k++) {
            za = fmaf(hv[k], Wa[k], za);
            zb = fmaf(hv[k], Wb[k], zb);
        }
    }
    out[idx] = __expf(za);
    out[(size_t)T_ * B_ + idx] =
        fmaxf(zb, 0.0f) + __logf(1.0f + __expf(-fabsf(zb)));
}

extern "C" void kernel_launch(void* const* d_in, const int* in_sizes, int n_in,
                              void* d_out, int out_size)
{
    const float *x = 0, *Wih = 0, *Whh = 0, *bih = 0, *bhh = 0;
    const float *Wa = 0, *ba = 0, *Wb = 0, *bb = 0;
    const int *lens = 0;
    int seen80 = 0, seen20 = 0, seen1 = 0;
    for (int i = 0; i < n_in; i++) {
        int s = in_sizes[i];
        if      (s == T_ * B_ * I_) x    = (const float*)d_in[i];
        else if (s == B_)           lens = (const int*)d_in[i];
        else if (s == 4*H_ * I_)    Wih  = (const float*)d_in[i];
        else if (s == 4*H_ * H_)    Whh  = (const float*)d_in[i];
        else if (s == 4*H_) { if (seen80++ == 0) bih = (const float*)d_in[i]; else bhh = (const float*)d_in[i]; }
        else if (s == H_)   { if (seen20++ == 0) Wa  = (const float*)d_in[i]; else Wb  = (const float*)d_in[i]; }
        else if (s == 1)    { if (seen1++  == 0) ba  = (const float*)d_in[i]; else bb  = (const float*)d_in[i]; }
    }

    float* out = (float*)d_out;
    xg_kernel<<<512 * 8, 160>>>(x, lens, Wih, bih, bhh);
    recur_kernel<<<512, 128>>>(lens, Whh);
    head_kernel<<<(T_ * B_) / 256, 256>>>(lens, Wa, ba, Wb, bb, out);
}